// round 17
// baseline (speedup 1.0000x reference)
#include <cuda_runtime.h>
#include <cuda_bf16.h>
#include <cstdint>

// SQEmbedding fully-fused flash-style, mma.sync(bf16) + cp.async.
// B=8,T=4096,D=64,M=1024,N=32768.
#define BB 8
#define TT 4096
#define DD 64
#define MM 1024
#define NN (BB * TT)
#define ROWS 32
#define NTILES (NN / ROWS)      // 1024
#define THREADS 512
#define NWARP 16
#define NCH 8

// smem byte offsets
#define SM_EB   0                // 2 bufs x (Eh 16K + El 16K) = 65536
#define SM_XH   65536            // x hi [32][72] bf16 (144B rows)
#define SM_XL   70144            // x lo
#define SM_E2   74752            // 1024 f32
#define SM_X2   78848            // 32 f32
#define SM_LMX  78976            // [32][8] f32  per-warp logit max
#define SM_S2   80000            // [32][8] f32
#define SM_QS   81024            // [32][8] f32
#define SM_WMX  82048            // [32][8] f32  per-warp w max
#define SM_S1   83072            // [32][8] f32
#define SM_BI   84096            // [32][8] int
#define SM_FQ   85120            // [32][8] f32  q rescale factors
#define SM_ENT  86144            // 32 f32
#define SM_INV  86272            // 32 f32
#define SM_RED  86400            // 16 f32
#define SM_QR   86464            // [32][66] f32 = 8448 (also x2-partial scratch early)
#define SMEM_BYTES 94912

__device__ float g_e2[MM];
__device__ int   g_hist[MM];
__device__ float g_partial[NTILES];
__device__ __align__(16) __nv_bfloat16 g_eh[MM * DD];  // E bf16 hi, [code][d]
__device__ __align__(16) __nv_bfloat16 g_el[MM * DD];  // E bf16 lo

// ---------------- helpers ----------------
__device__ __forceinline__ uint32_t smem_u32(const void* p) {
    uint32_t a;
    asm("{ .reg .u64 t; cvta.to.shared.u64 t, %1; cvt.u32.u64 %0, t; }"
        : "=r"(a) : "l"(p));
    return a;
}
__device__ __forceinline__ void ldsm4(uint32_t* r, uint32_t a) {
    asm volatile("ldmatrix.sync.aligned.m8n8.x4.shared.b16 {%0,%1,%2,%3}, [%4];"
                 : "=r"(r[0]), "=r"(r[1]), "=r"(r[2]), "=r"(r[3]) : "r"(a));
}
__device__ __forceinline__ void ldsm2(uint32_t& r0, uint32_t& r1, uint32_t a) {
    asm volatile("ldmatrix.sync.aligned.m8n8.x2.shared.b16 {%0,%1}, [%2];"
                 : "=r"(r0), "=r"(r1) : "r"(a));
}
__device__ __forceinline__ void ldsm2t(uint32_t& r0, uint32_t& r1, uint32_t a) {
    asm volatile("ldmatrix.sync.aligned.m8n8.x2.trans.shared.b16 {%0,%1}, [%2];"
                 : "=r"(r0), "=r"(r1) : "r"(a));
}
__device__ __forceinline__ void mma16816(float* d, const uint32_t* a,
                                         uint32_t b0, uint32_t b1) {
    asm volatile(
        "mma.sync.aligned.m16n8k16.row.col.f32.bf16.bf16.f32 "
        "{%0,%1,%2,%3}, {%4,%5,%6,%7}, {%8,%9}, {%0,%1,%2,%3};"
        : "+f"(d[0]), "+f"(d[1]), "+f"(d[2]), "+f"(d[3])
        : "r"(a[0]), "r"(a[1]), "r"(a[2]), "r"(a[3]), "r"(b0), "r"(b1));
}
__device__ __forceinline__ void cpa16(uint32_t dst, const void* src) {
    asm volatile("cp.async.cg.shared.global [%0], [%1], 16;" :: "r"(dst), "l"(src));
}
template <int N>
__device__ __forceinline__ void cpwait() {
    asm volatile("cp.async.wait_group %0;" :: "n"(N));
}
__device__ __forceinline__ void bsplit(float v, unsigned short& h, unsigned short& l) {
    __nv_bfloat16 hb = __float2bfloat16(v);
    h = __bfloat16_as_ushort(hb);
    l = __bfloat16_as_ushort(__float2bfloat16(v - __bfloat162float(hb)));
}
__device__ __forceinline__ uint32_t pack2(unsigned short a, unsigned short b) {
    return (uint32_t)a | ((uint32_t)b << 16);
}
// one E chunk (hi+lo) into buf via cp.async, swizzled 128B rows
__device__ __forceinline__ void issueE(uint32_t sb, int ch, int buf, int tid) {
    const char* bh = (const char*)g_eh + ch * 16384;
    const char* bl = (const char*)g_el + ch * 16384;
    uint32_t base = sb + SM_EB + buf * 32768;
#pragma unroll
    for (int u = 0; u < 2; ++u) {
        int t = tid + u * 512;
        int row = t >> 3, col = t & 7;
        uint32_t off = row * 128 + ((col ^ (row & 7)) << 4);
        cpa16(base + off,         bh + row * 128 + col * 16);
        cpa16(base + 16384 + off, bl + row * 128 + col * 16);
    }
    asm volatile("cp.async.commit_group;");
}

// ---------------------------------------------------------------------------
__global__ void prep_all(const float* __restrict__ emb) {
    __shared__ float sred[16];
    int tid = threadIdx.x;
    int idx = blockIdx.x * 512 + tid;
    float v = emb[idx];
    __nv_bfloat16 h = __float2bfloat16(v);
    g_eh[idx] = h;
    g_el[idx] = __float2bfloat16(v - __bfloat162float(h));
    float s = v * v;
#pragma unroll
    for (int o = 16; o; o >>= 1) s += __shfl_xor_sync(~0u, s, o);
    if ((tid & 31) == 0) sred[tid >> 5] = s;
    __syncthreads();
    if (tid < 8) {
        g_e2[blockIdx.x * 8 + tid] = sred[2 * tid] + sred[2 * tid + 1];
        g_hist[blockIdx.x * 8 + tid] = 0;
    }
}

// ---------------------------------------------------------------------------
__global__ __launch_bounds__(THREADS, 1)
void sqembed_main(const float* __restrict__ x,
                  const float* __restrict__ lvq,
                  const float* __restrict__ gum,
                  const float* __restrict__ temp,
                  float* __restrict__ out) {
    extern __shared__ char smem[];
    float* s_e2  = (float*)(smem + SM_E2);
    float* s_x2  = (float*)(smem + SM_X2);
    float* s_lmx = (float*)(smem + SM_LMX);
    float* s_s2  = (float*)(smem + SM_S2);
    float* s_qs  = (float*)(smem + SM_QS);
    float* s_wmx = (float*)(smem + SM_WMX);
    float* s_s1  = (float*)(smem + SM_S1);
    int*   s_bi  = (int*)(smem + SM_BI);
    float* s_fq  = (float*)(smem + SM_FQ);
    float* s_ent = (float*)(smem + SM_ENT);
    float* s_inv = (float*)(smem + SM_INV);
    float* s_red = (float*)(smem + SM_RED);
    float* s_qr  = (float*)(smem + SM_QR);

    const uint32_t sb = smem_u32(smem);
    const int tid = threadIdx.x, lane = tid & 31, warp = tid >> 5;
    const int mt = warp & 1, ng = warp >> 1;
    const int n0 = blockIdx.x * ROWS, b = n0 / TT, t0 = n0 % TT;
    const float prec = __expf(-lvq[0]), hp = 0.5f * prec, invT = 1.0f / temp[0];

    issueE(sb, 0, 0, tid);
    issueE(sb, 1, 1, tid);

    // ---- x load, bf16-split, row-norm partials; e2 staging ----
    float x2p = 0.f;
#pragma unroll
    for (int k = 0; k < 4; ++k) {
        int i = tid + THREADS * k, r = i & 31, d = i >> 5;
        float v = x[(b * DD + d) * TT + t0 + r];
        unsigned short h, l;
        bsplit(v, h, l);
        *(unsigned short*)(smem + SM_XH + r * 144 + d * 2) = h;
        *(unsigned short*)(smem + SM_XL + r * 144 + d * 2) = l;
        x2p = fmaf(v, v, x2p);
    }
    s_qr[warp * 32 + lane] = x2p;          // scratch (before qred use)
    s_e2[tid] = g_e2[tid];
    s_e2[tid + 512] = g_e2[tid + 512];
    __syncthreads();
    if (tid < 32) {
        float s = 0.f;
#pragma unroll
        for (int k = 0; k < NWARP; ++k) s += s_qr[k * 32 + tid];
        s_x2[tid] = s;
    }

    // per-lane row ids (within CTA tile)
    const int r0 = mt * 16 + (lane >> 2), r1 = r0 + 8;
    const int x7 = lane & 7, gc1 = (lane >> 3) & 1;
    const int rb1 = ng * 16 + x7;
    const uint32_t ax = sb + SM_XH + (mt * 16 + (lane & 15)) * 144 + ((lane >> 4) & 1) * 16;

    // running per-row (2 rows/lane) stats + q accumulator
    float M[2]  = {-1e30f, -1e30f};
    float S2[2] = {0.f, 0.f};
    float Qe[2] = {0.f, 0.f};
    float CW[2] = {-1e30f, -1e30f};
    float S1[2] = {0.f, 0.f};
    int   BI[2] = {0x7fffffff, 0x7fffffff};
    float q[8][4] = {};

    // ================= fused chunk loop =================
#pragma unroll 1
    for (int ch = 0; ch < NCH; ++ch) {
        if (ch == NCH - 1) cpwait<0>(); else cpwait<1>();
        __syncthreads();
        const uint32_t eb = sb + SM_EB + (ch & 1) * 32768;

        // GEMM1: x (A) @ E^T (B) -> logits frags
        uint32_t ah[4][4], al[4][4];
#pragma unroll
        for (int ks = 0; ks < 4; ++ks) {
            ldsm4(ah[ks], ax + ks * 32);
            ldsm4(al[ks], ax + (SM_XL - SM_XH) + ks * 32);
        }
        float acc[2][4] = {}, acb[2][4] = {};
#pragma unroll
        for (int ks = 0; ks < 4; ++ks) {
#pragma unroll
            for (int nt = 0; nt < 2; ++nt) {
                uint32_t a0 = eb + (rb1 + nt * 8) * 128 + (((ks * 2 + gc1) ^ x7) << 4);
                uint32_t bh0, bh1, bl0, bl1;
                ldsm2(bh0, bh1, a0);
                ldsm2(bl0, bl1, a0 + 16384);
                mma16816(acc[nt], ah[ks], bh0, bh1);
                mma16816(acb[nt], al[ks], bh0, bh1);
                mma16816(acb[nt], ah[ks], bl0, bl1);
            }
        }
        // logits in regs
        const int cb = ch * 128 + ng * 16 + 2 * (lane & 3);
        float2 e2a = *(const float2*)&s_e2[cb];
        float2 e2b = *(const float2*)&s_e2[cb + 8];
        float X0 = s_x2[r0], X1 = s_x2[r1];
        float l[2][4];
        l[0][0] = prec * (acc[0][0] + acb[0][0]) - hp * (X0 + e2a.x);
        l[0][1] = prec * (acc[0][1] + acb[0][1]) - hp * (X0 + e2a.y);
        l[0][2] = prec * (acc[0][2] + acb[0][2]) - hp * (X1 + e2a.x);
        l[0][3] = prec * (acc[0][3] + acb[0][3]) - hp * (X1 + e2a.y);
        l[1][0] = prec * (acc[1][0] + acb[1][0]) - hp * (X0 + e2b.x);
        l[1][1] = prec * (acc[1][1] + acb[1][1]) - hp * (X0 + e2b.y);
        l[1][2] = prec * (acc[1][2] + acb[1][2]) - hp * (X1 + e2b.x);
        l[1][3] = prec * (acc[1][3] + acb[1][3]) - hp * (X1 + e2b.y);

        // gumbels (row, codes cb..cb+1, cb+8..cb+9) — 32B coalesced per 4-group
        const float* gp0 = gum + (size_t)(n0 + r0) * MM + cb;
        const float* gp1 = gum + (size_t)(n0 + r1) * MM + cb;
        float2 ga0 = *(const float2*)gp0, gb0 = *(const float2*)(gp0 + 8);
        float2 ga1 = *(const float2*)gp1, gb1 = *(const float2*)(gp1 + 8);
        float g[2][4] = {{ga0.x, ga0.y, gb0.x, gb0.y},
                         {ga1.x, ga1.y, gb1.x, gb1.y}};

        uint32_t ah2[4], al2[4];   // enc A-frags for GEMM2
#pragma unroll
        for (int rr = 0; rr < 2; ++rr) {
            float v0 = l[0][rr * 2], v1 = l[0][rr * 2 + 1];
            float v2 = l[1][rr * 2], v3 = l[1][rr * 2 + 1];
            // --- entropy softmax online (exact) ---
            float mloc = fmaxf(fmaxf(v0, v1), fmaxf(v2, v3));
            mloc = fmaxf(mloc, __shfl_xor_sync(~0u, mloc, 1));
            mloc = fmaxf(mloc, __shfl_xor_sync(~0u, mloc, 2));
            float Mn = fmaxf(M[rr], mloc);
            float d0 = v0 - Mn, d1 = v1 - Mn, d2 = v2 - Mn, d3 = v3 - Mn;
            float e0 = __expf(d0), e1 = __expf(d1), e2v = __expf(d2), e3 = __expf(d3);
            float sl = (e0 + e1) + (e2v + e3);
            float ql = fmaf(e0, d0, fmaf(e1, d1, fmaf(e2v, d2, e3 * d3)));
            sl += __shfl_xor_sync(~0u, sl, 1); sl += __shfl_xor_sync(~0u, sl, 2);
            ql += __shfl_xor_sync(~0u, ql, 1); ql += __shfl_xor_sync(~0u, ql, 2);
            float f = __expf(M[rr] - Mn);
            Qe[rr] = f * (Qe[rr] + (M[rr] - Mn) * S2[rr]) + ql;
            S2[rr] = f * S2[rr] + sl;
            // argmax (first-index) via exact equality
            int cand = 0x7fffffff;
            if (v3 == Mn) cand = cb + 9;
            if (v2 == Mn) cand = cb + 8;
            if (v1 == Mn) cand = cb + 1;
            if (v0 == Mn) cand = cb;
            cand = min(cand, __shfl_xor_sync(~0u, cand, 1));
            cand = min(cand, __shfl_xor_sync(~0u, cand, 2));
            BI[rr] = (Mn > M[rr]) ? cand : min(BI[rr], cand);
            M[rr] = Mn;
            // --- gumbel softmax online + q rescale ---
            float w0 = (v0 + g[rr][0]) * invT, w1 = (v1 + g[rr][1]) * invT;
            float w2 = (v2 + g[rr][2]) * invT, w3 = (v3 + g[rr][3]) * invT;
            float wl = fmaxf(fmaxf(w0, w1), fmaxf(w2, w3));
            wl = fmaxf(wl, __shfl_xor_sync(~0u, wl, 1));
            wl = fmaxf(wl, __shfl_xor_sync(~0u, wl, 2));
            float Cn = fmaxf(CW[rr], wl);
            float f1 = __expf(CW[rr] - Cn);
            float p0 = __expf(w0 - Cn), p1 = __expf(w1 - Cn);
            float p2 = __expf(w2 - Cn), p3 = __expf(w3 - Cn);
            float ps = (p0 + p1) + (p2 + p3);
            ps += __shfl_xor_sync(~0u, ps, 1); ps += __shfl_xor_sync(~0u, ps, 2);
            S1[rr] = S1[rr] * f1 + ps;
            CW[rr] = Cn;
#pragma unroll
            for (int t = 0; t < 8; ++t) {
                q[t][rr * 2] *= f1;
                q[t][rr * 2 + 1] *= f1;
            }
            // enc -> bf16 split -> A-frags (C-frag layout == A-frag layout)
            unsigned short h0, lo0, h1, lo1, h2, lo2, h3, lo3;
            bsplit(p0, h0, lo0); bsplit(p1, h1, lo1);
            bsplit(p2, h2, lo2); bsplit(p3, h3, lo3);
            ah2[rr]     = pack2(h0, h1);   // nt0 row rr
            ah2[rr + 2] = pack2(h2, h3);   // nt1 row rr
            al2[rr]     = pack2(lo0, lo1);
            al2[rr + 2] = pack2(lo2, lo3);
        }

        // GEMM2: q += enc (A) @ E chunk (B), k = warp's 16 codes, n = 64 d
#pragma unroll
        for (int t = 0; t < 8; ++t) {
            uint32_t ba = eb + (ng * 16 + (lane & 15)) * 128 + ((t ^ x7) << 4);
            uint32_t bh0, bh1, bl0, bl1;
            ldsm2t(bh0, bh1, ba);
            ldsm2t(bl0, bl1, ba + 16384);
            mma16816(q[t], ah2, bh0, bh1);
            mma16816(q[t], al2, bh0, bh1);
            mma16816(q[t], ah2, bl0, bl1);
        }
        __syncthreads();
        if (ch + 2 < NCH) issueE(sb, ch + 2, ch & 1, tid);
    }

    // ================= final merges =================
    if ((lane & 3) == 0) {
        int o0 = r0 * 8 + ng, o1 = r1 * 8 + ng;
        s_lmx[o0] = M[0];  s_lmx[o1] = M[1];
        s_s2[o0]  = S2[0]; s_s2[o1]  = S2[1];
        s_qs[o0]  = Qe[0]; s_qs[o1]  = Qe[1];
        s_wmx[o0] = CW[0]; s_wmx[o1] = CW[1];
        s_s1[o0]  = S1[0]; s_s1[o1]  = S1[1];
        s_bi[o0]  = BI[0]; s_bi[o1]  = BI[1];
    }
    __syncthreads();
    if (tid < 32) {
        int r = tid;
        float Mg = -1e30f, Wg = -1e30f;
#pragma unroll
        for (int w = 0; w < 8; ++w) {
            Mg = fmaxf(Mg, s_lmx[r * 8 + w]);
            Wg = fmaxf(Wg, s_wmx[r * 8 + w]);
        }
        float s2g = 0.f, qg = 0.f, s1g = 0.f;
        int big = 0x7fffffff;
#pragma unroll
        for (int w = 0; w < 8; ++w) {
            float dm = s_lmx[r * 8 + w] - Mg;
            float fw = __expf(dm);
            s2g += s_s2[r * 8 + w] * fw;
            qg  += (s_qs[r * 8 + w] + dm * s_s2[r * 8 + w]) * fw;
            if (s_lmx[r * 8 + w] == Mg) big = min(big, s_bi[r * 8 + w]);
            float fq = __expf(s_wmx[r * 8 + w] - Wg);
            s1g += s_s1[r * 8 + w] * fq;
            s_fq[r * 8 + w] = fq;
        }
        s_ent[r] = qg / s2g - __logf(s2g);
        s_inv[r] = 1.0f / s1g;
        atomicAdd(&g_hist[big], 1);
    }
    __syncthreads();

    // deterministic ordered q reduction across the 8 ng warps
#pragma unroll 1
    for (int s = 0; s < 8; ++s) {
        if (ng == s) {
            float f0 = s_fq[r0 * 8 + ng], f1v = s_fq[r1 * 8 + ng];
            if (s == 0) {
#pragma unroll
                for (int t = 0; t < 8; ++t) {
                    int c = t * 8 + 2 * (lane & 3);
                    s_qr[r0 * 66 + c]     = q[t][0] * f0;
                    s_qr[r0 * 66 + c + 1] = q[t][1] * f0;
                    s_qr[r1 * 66 + c]     = q[t][2] * f1v;
                    s_qr[r1 * 66 + c + 1] = q[t][3] * f1v;
                }
            } else {
#pragma unroll
                for (int t = 0; t < 8; ++t) {
                    int c = t * 8 + 2 * (lane & 3);
                    s_qr[r0 * 66 + c]     += q[t][0] * f0;
                    s_qr[r0 * 66 + c + 1] += q[t][1] * f0;
                    s_qr[r1 * 66 + c]     += q[t][2] * f1v;
                    s_qr[r1 * 66 + c + 1] += q[t][3] * f1v;
                }
            }
        }
        __syncthreads();
    }

    // ---- epilogue: scale, write out, loss ----
    float myloss = 0.f;
#pragma unroll
    for (int k = 0; k < 4; ++k) {
        int i = tid + THREADS * k, r = i & 31, d = i >> 5;
        float qv = s_qr[r * 66 + d] * s_inv[r];
        out[(b * DD + d) * TT + t0 + r] = qv;
        float xh = __bfloat162float(__ushort_as_bfloat16(
            *(unsigned short*)(smem + SM_XH + r * 144 + d * 2)));
        float xl = __bfloat162float(__ushort_as_bfloat16(
            *(unsigned short*)(smem + SM_XL + r * 144 + d * 2)));
        float dx = (xh + xl) - qv;
        myloss = fmaf(dx, dx, myloss);
    }
    myloss *= hp;
    if (tid < ROWS) myloss += s_ent[tid];
#pragma unroll
    for (int o = 16; o; o >>= 1) myloss += __shfl_xor_sync(~0u, myloss, o);
    if (lane == 0) s_red[warp] = myloss;
    __syncthreads();
    if (tid == 0) {
        float s = 0.f;
#pragma unroll
        for (int w2 = 0; w2 < NWARP; ++w2) s += s_red[w2];
        g_partial[blockIdx.x] = s;
    }
}

// ---------------------------------------------------------------------------
__global__ void final_kernel(float* __restrict__ out, int out_size) {
    __shared__ float sl[32], sp[32];
    int tid = threadIdx.x;
    float v = g_partial[tid];
    float a = (float)g_hist[tid] * (1.0f / (float)NN);
    float pe = a * __logf(a + 1e-10f);
#pragma unroll
    for (int o = 16; o; o >>= 1) {
        v  += __shfl_xor_sync(~0u, v, o);
        pe += __shfl_xor_sync(~0u, pe, o);
    }
    if ((tid & 31) == 0) { sl[tid >> 5] = v; sp[tid >> 5] = pe; }
    __syncthreads();
    if (tid == 0) {
        float lv = 0.f, pv = 0.f;
#pragma unroll
        for (int i = 0; i < 32; ++i) { lv += sl[i]; pv += sp[i]; }
        if (out_size >= NN * DD + 2) {
            out[NN * DD]     = lv / (float)BB;
            out[NN * DD + 1] = __expf(-pv);
        }
    }
}

// ---------------------------------------------------------------------------
extern "C" void kernel_launch(void* const* d_in, const int* in_sizes, int n_in,
                              void* d_out, int out_size) {
    (void)in_sizes; (void)n_in;
    const float* x    = (const float*)d_in[0];
    const float* emb  = (const float*)d_in[1];
    const float* lvq  = (const float*)d_in[2];
    const float* gum  = (const float*)d_in[3];
    const float* temp = (const float*)d_in[4];
    float* out = (float*)d_out;

    cudaFuncSetAttribute(sqembed_main,
                         cudaFuncAttributeMaxDynamicSharedMemorySize, SMEM_BYTES);

    prep_all<<<128, 512>>>(emb);
    sqembed_main<<<NTILES, THREADS, SMEM_BYTES>>>(x, lvq, gum, temp, out);
    final_kernel<<<1, 1024>>>(out, out_size);
}